// round 2
// baseline (speedup 1.0000x reference)
#include <cuda_runtime.h>
#include <math.h>

#define BB 64
#define CINN 64
#define COUTT 128
#define NPIX 1024
#define TC 4

typedef unsigned long long ull;

__device__ float g_psum[COUTT * BB];
__device__ float g_psumsq[COUTT * BB];
__device__ float g_scale[COUTT];
__device__ float g_shift[COUTT];

__device__ __forceinline__ void fma2(ull &acc, ull a, ull b) {
    asm("fma.rn.f32x2 %0, %1, %2, %0;" : "+l"(acc) : "l"(a), "l"(b));
}

// floor((a)/3) for a >= -24
__device__ __forceinline__ int fd3(int a) { return (a + 24) / 3 - 8; }

// Fused: per-CTA (b, 4-cout tile): 9-tap 1x1 GEMM into SMEM, then gather+sum+maxpool,
// write pre-BN result to out, emit per-(co,b) partial sums for BN.
__global__ void __launch_bounds__(512, 1)
fused_kernel(const float* __restrict__ x, const int* __restrict__ hh,
             const int* __restrict__ wwp, const float* __restrict__ weight,
             const float* __restrict__ bias, float* __restrict__ out)
{
    extern __shared__ float smem[];
    float*  Ys  = smem;                        // 36864 floats (9*4*1024), written post-GEMM
    float*  Xs  = smem;                        // aliases first 16384 floats during GEMM
    float2* Ws2 = (float2*)(smem + 36864);     // 3072 float2 (4 co * 64 cin * 12-pad taps)

    const int tid    = threadIdx.x;
    const int b      = blockIdx.y;
    const int co0    = blockIdx.x * TC;
    const int co_l   = tid >> 7;
    const int lane128 = tid & 127;

    // ---- load weights as duplicated f32 pairs (for f32x2 broadcast multiply) ----
    for (int i = tid; i < TC * CINN * 9; i += 512) {
        int c   = i / (CINN * 9);
        int r   = i - c * (CINN * 9);
        int ci  = r / 9;
        int tap = r - ci * 9;
        float wv = weight[(co0 + c) * (CINN * 9) + ci * 9 + tap];
        Ws2[(c * CINN + ci) * 12 + tap] = make_float2(wv, wv);
    }

    // ---- GEMM phase: Y[tap][co_l][pix] = sum_cin W * x ----
    ull acc[9][4];
#pragma unroll
    for (int t = 0; t < 9; t++)
#pragma unroll
        for (int j = 0; j < 4; j++) acc[t][j] = 0ull;

    const int g0 = lane128 * 4;   // 4 consecutive pixels
    const int g1 = g0 + 512;      // second half

    for (int chunk = 0; chunk < 4; chunk++) {
        __syncthreads();  // protect Xs reuse (and Ws2 visibility on first iter)
        const float4* xg  = (const float4*)(x + (size_t)b * CINN * NPIX + chunk * 16 * NPIX);
        float4*       xs4 = (float4*)Xs;
#pragma unroll
        for (int j = 0; j < 8; j++) xs4[tid + 512 * j] = xg[tid + 512 * j];
        __syncthreads();
#pragma unroll 4
        for (int ci = 0; ci < 16; ci++) {
            int cing = chunk * 16 + ci;
            ulonglong2 xa = *(const ulonglong2*)&Xs[ci * NPIX + g0];
            ulonglong2 xb = *(const ulonglong2*)&Xs[ci * NPIX + g1];
            const ull* wp = (const ull*)&Ws2[(co_l * CINN + cing) * 12];
#pragma unroll
            for (int tap = 0; tap < 9; tap++) {
                ull wq = wp[tap];
                fma2(acc[tap][0], xa.x, wq);
                fma2(acc[tap][1], xa.y, wq);
                fma2(acc[tap][2], xb.x, wq);
                fma2(acc[tap][3], xb.y, wq);
            }
        }
    }
    __syncthreads();  // all Xs reads done; Ys may overwrite the aliased region
#pragma unroll
    for (int tap = 0; tap < 9; tap++) {
        ulonglong2 va; va.x = acc[tap][0]; va.y = acc[tap][1];
        *(ulonglong2*)&Ys[(tap * TC + co_l) * NPIX + g0] = va;
        ulonglong2 vb; vb.x = acc[tap][2]; vb.y = acc[tap][3];
        *(ulonglong2*)&Ys[(tap * TC + co_l) * NPIX + g1] = vb;
    }
    __syncthreads();

    // ---- per-sample offset tables (uniform across CTA) ----
    int dh = 96 / hh[b];  if (dh < 1) dh = 1;
    int dw = 96 / wwp[b]; if (dw < 1) dw = 1;

    int  rv[3][2];
    bool rsel[3][3];
    int  dc[3][3];
#pragma unroll
    for (int k = 0; k < 3; k++) {
        int d0 = fd3(0 + (k - 1) * dh);
        int d1 = fd3(1 + (k - 1) * dh);
        int d2 = fd3(2 + (k - 1) * dh);
        rv[k][0] = d0; rv[k][1] = d2;
        rsel[k][0] = false;
        rsel[k][1] = (d1 != d0);
        rsel[k][2] = (d2 != d0);
#pragma unroll
        for (int s = 0; s < 3; s++) dc[k][s] = fd3(s + (k - 1) * dw);
    }

    const float bias_v = bias[co0 + co_l];
    float lsum = 0.f, lsq = 0.f;

    // ---- combine: 8 pooled outputs per thread (lane-stride-1 for conflict-free LDS) ----
#pragma unroll 1
    for (int j = 0; j < 8; j++) {
        int pix = lane128 + (j << 7);
        int py  = pix >> 5;
        int px  = pix & 31;

        float RS[3][2][3];
#pragma unroll
        for (int ki = 0; ki < 3; ki++) {
#pragma unroll
            for (int v = 0; v < 2; v++) {
                int  row = py + rv[ki][v];
                bool rok = (unsigned)row < 32u;
                int  rb  = row * 32;
#pragma unroll
                for (int s = 0; s < 3; s++) {
                    float a = 0.f;
#pragma unroll
                    for (int kj = 0; kj < 3; kj++) {
                        int col = px + dc[kj][s];
                        if (rok && (unsigned)col < 32u)
                            a += Ys[((ki * 3 + kj) * TC + co_l) * NPIX + rb + col];
                    }
                    RS[ki][v][s] = a;
                }
            }
        }
        float m = -INFINITY;
#pragma unroll
        for (int r = 0; r < 3; r++) {
#pragma unroll
            for (int s = 0; s < 3; s++) {
                float v0 = rsel[0][r] ? RS[0][1][s] : RS[0][0][s];
                float v1 = rsel[1][r] ? RS[1][1][s] : RS[1][0][s];
                float v2 = rsel[2][r] ? RS[2][1][s] : RS[2][0][s];
                float cv = bias_v + v0 + v1 + v2;
                m = fmaxf(m, cv);
            }
        }
        out[((size_t)b * COUTT + co0 + co_l) * NPIX + pix] = m;
        lsum += m;
        lsq  += m * m;
    }

    // ---- deterministic per-(co,b) partial sums for BN ----
#pragma unroll
    for (int o = 16; o > 0; o >>= 1) {
        lsum += __shfl_xor_sync(0xFFFFFFFFu, lsum, o);
        lsq  += __shfl_xor_sync(0xFFFFFFFFu, lsq,  o);
    }
    __syncthreads();                 // done reading Ys/Ws2
    float* red = (float*)Ws2;        // reuse weight region: 16 warps * 2 floats
    int warp = tid >> 5;
    if ((tid & 31) == 0) { red[warp * 2] = lsum; red[warp * 2 + 1] = lsq; }
    __syncthreads();
    if (tid < TC) {
        int c = tid;
        float s = red[(4 * c + 0) * 2] + red[(4 * c + 1) * 2] +
                  red[(4 * c + 2) * 2] + red[(4 * c + 3) * 2];
        float q = red[(4 * c + 0) * 2 + 1] + red[(4 * c + 1) * 2 + 1] +
                  red[(4 * c + 2) * 2 + 1] + red[(4 * c + 3) * 2 + 1];
        g_psum  [(co0 + c) * BB + b] = s;
        g_psumsq[(co0 + c) * BB + b] = q;
    }
}

__global__ void stats_kernel(const float* __restrict__ gamma,
                             const float* __restrict__ beta)
{
    int c = threadIdx.x;  // 128 threads
    float s = 0.f, q = 0.f;
#pragma unroll 8
    for (int i = 0; i < BB; i++) { s += g_psum[c * BB + i]; q += g_psumsq[c * BB + i]; }
    const float inv = 1.0f / 65536.0f;
    float mean = s * inv;
    float var  = q * inv - mean * mean;
    float sc   = gamma[c] * rsqrtf(var + 1e-5f);
    g_scale[c] = sc;
    g_shift[c] = beta[c] - mean * sc;
}

__global__ void __launch_bounds__(1024)
apply_kernel(float* __restrict__ out)
{
    int i = blockIdx.x * 1024 + threadIdx.x;  // float4 index; grid covers 2097152 exactly
    int c = (i >> 8) & 127;                   // 256 float4 per (b,co) plane
    float4 v = ((float4*)out)[i];
    float sc = g_scale[c], sh = g_shift[c];
    v.x = fmaxf(fmaf(v.x, sc, sh), 0.f);
    v.y = fmaxf(fmaf(v.y, sc, sh), 0.f);
    v.z = fmaxf(fmaf(v.z, sc, sh), 0.f);
    v.w = fmaxf(fmaf(v.w, sc, sh), 0.f);
    ((float4*)out)[i] = v;
}

extern "C" void kernel_launch(void* const* d_in, const int* in_sizes, int n_in,
                              void* d_out, int out_size)
{
    const float* x      = (const float*)d_in[0];
    const int*   h      = (const int*)  d_in[1];
    const int*   w      = (const int*)  d_in[2];
    const float* weight = (const float*)d_in[3];
    const float* bias   = (const float*)d_in[4];
    const float* gamma  = (const float*)d_in[5];
    const float* beta   = (const float*)d_in[6];
    float* out = (float*)d_out;

    const int shmem = 36864 * 4 + 3072 * 8;  // 172032 bytes
    cudaFuncSetAttribute(fused_kernel, cudaFuncAttributeMaxDynamicSharedMemorySize, shmem);

    dim3 grid(COUTT / TC, BB);  // (32, 64)
    fused_kernel<<<grid, 512, shmem>>>(x, h, w, weight, bias, out);
    stats_kernel<<<1, 128>>>(gamma, beta);
    apply_kernel<<<2048, 1024>>>(out);
}

// round 4
// speedup vs baseline: 1.6180x; 1.6180x over previous
#include <cuda_runtime.h>
#include <cuda_bf16.h>
#include <math.h>
#include <cstdint>

#define BB 64
#define CINN 64
#define COUTT 128
#define NPIX 1024
#define TC 4

// fused SMEM (bytes): A double buffer 2x(hi32K+lo32K)=131072, W at 131072 (2x5760),
// Ys[36864 f32]=147456 aliases everything post-GEMM, red at 147456.
#define SM_AB 0
#define SM_W  131072
#define SM_RED 147456
#define SMEM_TOTAL 147584

__device__ uint4 A_g[BB * 4 * 4096];   // 16MB: per (b,chunk) 64KB: hi plane 32KB | lo plane 32KB
__device__ float g_psum[COUTT * BB];
__device__ float g_psumsq[COUTT * BB];
__device__ float g_scale[COUTT];
__device__ float g_shift[COUTT];

__device__ __forceinline__ uint32_t smem_u32(const void* p) {
    uint32_t a;
    asm("{ .reg .u64 t; cvta.to.shared.u64 t, %1; cvt.u32.u64 %0, t; }" : "=r"(a) : "l"(p));
    return a;
}
__device__ __forceinline__ void cp16(uint32_t dst, const void* src) {
    asm volatile("cp.async.cg.shared.global [%0], [%1], 16;" :: "r"(dst), "l"(src) : "memory");
}
__device__ __forceinline__ void ldmat4(uint32_t* r, uint32_t addr) {
    asm volatile("ldmatrix.sync.aligned.m8n8.x4.shared.b16 {%0,%1,%2,%3}, [%4];"
        : "=r"(r[0]), "=r"(r[1]), "=r"(r[2]), "=r"(r[3]) : "r"(addr));
}
__device__ __forceinline__ void mma16816(float* d, const uint32_t* a, const uint32_t* b) {
    asm volatile("mma.sync.aligned.m16n8k16.row.col.f32.bf16.bf16.f32 "
        "{%0,%1,%2,%3}, {%4,%5,%6,%7}, {%8,%9}, {%0,%1,%2,%3};"
        : "+f"(d[0]), "+f"(d[1]), "+f"(d[2]), "+f"(d[3])
        : "r"(a[0]), "r"(a[1]), "r"(a[2]), "r"(a[3]), "r"(b[0]), "r"(b[1]));
}
__device__ __forceinline__ uint32_t pkbf(float a, float b) {
    unsigned short u0 = __bfloat16_as_ushort(__float2bfloat16(a));
    unsigned short u1 = __bfloat16_as_ushort(__float2bfloat16(b));
    return (uint32_t)u0 | ((uint32_t)u1 << 16);
}
__device__ __forceinline__ int fd3(int a) { return (a + 24) / 3 - 8; }  // floor(a/3), a>=-24

// ---- prologue: per (chunk,b) build hi/lo bf16 planes in ldmatrix-swizzled layout ----
// plane row px: 32B = k0..15 bf16; 16B halves swapped when (px>>2)&1.
__global__ void __launch_bounds__(512) build_A(const float* __restrict__ x)
{
    extern __shared__ float Xs[];   // [16][1032]
    const int tid = threadIdx.x, chunk = blockIdx.x, b = blockIdx.y;
    const float4* xg = (const float4*)(x + (size_t)b * CINN * NPIX + chunk * 16 * NPIX);
#pragma unroll
    for (int j = 0; j < 8; j++) {
        int idx = tid + 512 * j;
        int ci = idx >> 8, px4 = idx & 255;
        *(float4*)(Xs + ci * 1032 + px4 * 4) = xg[idx];
    }
    __syncthreads();
    uint4* pb = A_g + (size_t)(b * 4 + chunk) * 4096;
#pragma unroll
    for (int rep = 0; rep < 2; rep++) {
        int px = tid + rep * 512;
        uint32_t hu[8], lu[8];
#pragma unroll
        for (int j = 0; j < 8; j++) {
            float v0 = Xs[(2 * j) * 1032 + px];
            float v1 = Xs[(2 * j + 1) * 1032 + px];
            float h0 = __bfloat162float(__float2bfloat16(v0));
            float h1 = __bfloat162float(__float2bfloat16(v1));
            hu[j] = pkbf(v0, v1);
            lu[j] = pkbf(v0 - h0, v1 - h1);
        }
        int s = (px >> 2) & 1;
        uint4 u;
        u.x = hu[0]; u.y = hu[1]; u.z = hu[2]; u.w = hu[3];
        pb[px * 2 + (0 ^ s)] = u;
        u.x = hu[4]; u.y = hu[5]; u.z = hu[6]; u.w = hu[7];
        pb[px * 2 + (1 ^ s)] = u;
        u.x = lu[0]; u.y = lu[1]; u.z = lu[2]; u.w = lu[3];
        pb[2048 + px * 2 + (0 ^ s)] = u;
        u.x = lu[4]; u.y = lu[5]; u.z = lu[6]; u.w = lu[7];
        pb[2048 + px * 2 + (1 ^ s)] = u;
    }
}

__global__ void __launch_bounds__(512, 1)
fused_kernel(const int* __restrict__ hh, const int* __restrict__ wwp,
             const float* __restrict__ weight, const float* __restrict__ bias,
             float* __restrict__ out)
{
    extern __shared__ char smem[];
    const uint32_t sb = smem_u32(smem);
    float* Ys = (float*)smem;
    const int tid = threadIdx.x, wid = tid >> 5, l = tid & 31;
    const int b = blockIdx.y, co0 = blockIdx.x * TC;

    // zero W region (rows 36..39 must be 0)
    for (int i = tid; i < 11520 / 4; i += 512) *(uint32_t*)(smem + SM_W + 4 * i) = 0u;
    __syncthreads();
    // weights: row n = tap*4+c, [n][k] k=ci, 144B stride; hi at 0, lo at 5760
    for (int i = tid; i < TC * CINN * 9; i += 512) {
        int c = i / 576, r = i - c * 576, ci = r / 9, tap = r - ci * 9;
        float w = weight[(co0 + c) * 576 + ci * 9 + tap];
        float wh = __bfloat162float(__float2bfloat16(w));
        int off = SM_W + (tap * 4 + c) * 144 + ci * 2;
        *(unsigned short*)(smem + off)        = __bfloat16_as_ushort(__float2bfloat16(w));
        *(unsigned short*)(smem + off + 5760) = __bfloat16_as_ushort(__float2bfloat16(w - wh));
    }
    // stage chunk 0
    {
        const char* src = (const char*)(A_g + (size_t)(b * 4) * 4096);
#pragma unroll
        for (int j = 0; j < 8; j++) {
            int i = tid + 512 * j;
            cp16(sb + SM_AB + i * 16, src + i * 16);
        }
        asm volatile("cp.async.commit_group;" ::: "memory");
    }
    __syncthreads();

    float acc[4][5][4];
#pragma unroll
    for (int mt = 0; mt < 4; mt++)
#pragma unroll
        for (int nt = 0; nt < 5; nt++)
#pragma unroll
            for (int k = 0; k < 4; k++) acc[mt][nt][k] = 0.f;

    const int lq = l & 3, ln = l >> 2;
    const int m = l & 15, kh = l >> 4;
    const uint32_t aswz = (uint32_t)((kh ^ ((m >> 2) & 1)) << 4) + m * 32;
    const int px0 = wid * 64;

    for (int ch = 0; ch < 4; ch++) {
        asm volatile("cp.async.wait_group 0;" ::: "memory");
        __syncthreads();
        if (ch < 3) {
            const char* src = (const char*)(A_g + (size_t)(b * 4 + ch + 1) * 4096);
            uint32_t dbuf = sb + SM_AB + ((ch + 1) & 1) * 65536;
#pragma unroll
            for (int j = 0; j < 8; j++) {
                int i = tid + 512 * j;
                cp16(dbuf + i * 16, src + i * 16);
            }
            asm volatile("cp.async.commit_group;" ::: "memory");
        }
        // B fragments for this chunk
        uint32_t bh[5][2], bl[5][2];
#pragma unroll
        for (int nt = 0; nt < 5; nt++) {
            int base = SM_W + (nt * 8 + ln) * 144 + ch * 32 + 4 * lq;
            bh[nt][0] = *(uint32_t*)(smem + base);
            bh[nt][1] = *(uint32_t*)(smem + base + 16);
            bl[nt][0] = *(uint32_t*)(smem + base + 5760);
            bl[nt][1] = *(uint32_t*)(smem + base + 5776);
        }
        const uint32_t abase = sb + SM_AB + (ch & 1) * 65536;
#pragma unroll
        for (int mt = 0; mt < 4; mt++) {
            uint32_t ah[4], al[4];
            uint32_t ra = abase + (uint32_t)(px0 + mt * 16) * 32 + aswz;
            ldmat4(ah, ra);
            ldmat4(al, ra + 32768);
#pragma unroll
            for (int nt = 0; nt < 5; nt++) {
                mma16816(acc[mt][nt], ah, bh[nt]);
                mma16816(acc[mt][nt], al, bh[nt]);
                mma16816(acc[mt][nt], ah, bl[nt]);
            }
        }
    }
    __syncthreads();   // all SMEM A/W reads done; Ys may overwrite

    // readout: D frag (m16n8): d0/d1 row l/4 cols 2lq,2lq+1; d2/d3 row l/4+8
#pragma unroll
    for (int mt = 0; mt < 4; mt++)
#pragma unroll
        for (int nt = 0; nt < 5; nt++) {
            int c0 = nt * 8 + 2 * lq;
            if (nt == 4 && lq >= 2) continue;  // cols 36..39 unused
            int px = px0 + mt * 16 + ln;
            Ys[c0 * NPIX + px]            = acc[mt][nt][0];
            Ys[(c0 + 1) * NPIX + px]      = acc[mt][nt][1];
            Ys[c0 * NPIX + px + 8]        = acc[mt][nt][2];
            Ys[(c0 + 1) * NPIX + px + 8]  = acc[mt][nt][3];
        }
    __syncthreads();

    // ---- combine (verified): Ys col c = tap*4 + co_l ----
    const int co_l = tid >> 7, lane128 = tid & 127;
    int dh = 96 / hh[b];  if (dh < 1) dh = 1;
    int dw = 96 / wwp[b]; if (dw < 1) dw = 1;
    int rv[3][2]; bool rsel[3][3]; int dc[3][3];
#pragma unroll
    for (int k = 0; k < 3; k++) {
        int d0 = fd3((k - 1) * dh), d1 = fd3(1 + (k - 1) * dh), d2 = fd3(2 + (k - 1) * dh);
        rv[k][0] = d0; rv[k][1] = d2;
        rsel[k][0] = false; rsel[k][1] = (d1 != d0); rsel[k][2] = (d2 != d0);
#pragma unroll
        for (int s = 0; s < 3; s++) dc[k][s] = fd3(s + (k - 1) * dw);
    }
    const float bias_v = bias[co0 + co_l];
    float lsum = 0.f, lsq = 0.f;
#pragma unroll 1
    for (int j = 0; j < 8; j++) {
        int pix = lane128 + (j << 7), py = pix >> 5, px = pix & 31;
        float RS[3][2][3];
#pragma unroll
        for (int ki = 0; ki < 3; ki++)
#pragma unroll
            for (int v = 0; v < 2; v++) {
                int row = py + rv[ki][v];
                bool rok = (unsigned)row < 32u;
                int rb = row * 32;
#pragma unroll
                for (int s = 0; s < 3; s++) {
                    float a = 0.f;
#pragma unroll
                    for (int kj = 0; kj < 3; kj++) {
                        int col = px + dc[kj][s];
                        if (rok && (unsigned)col < 32u)
                            a += Ys[((ki * 3 + kj) * TC + co_l) * NPIX + rb + col];
                    }
                    RS[ki][v][s] = a;
                }
            }
        float mx = -INFINITY;
#pragma unroll
        for (int r = 0; r < 3; r++)
#pragma unroll
            for (int s = 0; s < 3; s++) {
                float v0 = rsel[0][r] ? RS[0][1][s] : RS[0][0][s];
                float v1 = rsel[1][r] ? RS[1][1][s] : RS[1][0][s];
                float v2 = rsel[2][r] ? RS[2][1][s] : RS[2][0][s];
                mx = fmaxf(mx, bias_v + v0 + v1 + v2);
            }
        out[((size_t)b * COUTT + co0 + co_l) * NPIX + pix] = mx;
        lsum += mx; lsq += mx * mx;
    }
#pragma unroll
    for (int o = 16; o > 0; o >>= 1) {
        lsum += __shfl_xor_sync(0xFFFFFFFFu, lsum, o);
        lsq  += __shfl_xor_sync(0xFFFFFFFFu, lsq,  o);
    }
    __syncthreads();
    float* red = (float*)(smem + SM_RED);
    if (l == 0) { red[wid * 2] = lsum; red[wid * 2 + 1] = lsq; }
    __syncthreads();
    if (tid < TC) {
        int c = tid;
        float s = red[8*c] + red[8*c+2] + red[8*c+4] + red[8*c+6];
        float q = red[8*c+1] + red[8*c+3] + red[8*c+5] + red[8*c+7];
        g_psum[(co0 + c) * BB + b] = s;
        g_psumsq[(co0 + c) * BB + b] = q;
    }
}

__global__ void stats_kernel(const float* __restrict__ gamma, const float* __restrict__ beta)
{
    int c = threadIdx.x;
    float s = 0.f, q = 0.f;
#pragma unroll 8
    for (int i = 0; i < BB; i++) { s += g_psum[c * BB + i]; q += g_psumsq[c * BB + i]; }
    const float inv = 1.0f / 65536.0f;
    float mean = s * inv, var = q * inv - mean * mean;
    float sc = gamma[c] * rsqrtf(var + 1e-5f);
    g_scale[c] = sc;
    g_shift[c] = beta[c] - mean * sc;
}

__global__ void __launch_bounds__(1024)
apply_kernel(float* __restrict__ out)
{
    int i = blockIdx.x * 1024 + threadIdx.x;
    int c = (i >> 8) & 127;
    float4 v = ((float4*)out)[i];
    float sc = g_scale[c], sh = g_shift[c];
    v.x = fmaxf(fmaf(v.x, sc, sh), 0.f);
    v.y = fmaxf(fmaf(v.y, sc, sh), 0.f);
    v.z = fmaxf(fmaf(v.z, sc, sh), 0.f);
    v.w = fmaxf(fmaf(v.w, sc, sh), 0.f);
    ((float4*)out)[i] = v;
}

extern "C" void kernel_launch(void* const* d_in, const int* in_sizes, int n_in,
                              void* d_out, int out_size)
{
    const float* x      = (const float*)d_in[0];
    const int*   h      = (const int*)  d_in[1];
    const int*   w      = (const int*)  d_in[2];
    const float* weight = (const float*)d_in[3];
    const float* bias   = (const float*)d_in[4];
    const float* gamma  = (const float*)d_in[5];
    const float* beta   = (const float*)d_in[6];
    float* out = (float*)d_out;

    cudaFuncSetAttribute(build_A, cudaFuncAttributeMaxDynamicSharedMemorySize, 66048);
    cudaFuncSetAttribute(fused_kernel, cudaFuncAttributeMaxDynamicSharedMemorySize, SMEM_TOTAL);

    build_A<<<dim3(4, BB), 512, 66048>>>(x);
    fused_kernel<<<dim3(COUTT / TC, BB), 512, SMEM_TOTAL>>>(h, w, weight, bias, out);
    stats_kernel<<<1, 128>>>(gamma, beta);
    apply_kernel<<<2048, 1024>>>(out);
}

// round 5
// speedup vs baseline: 1.6852x; 1.0415x over previous
#include <cuda_runtime.h>
#include <cuda_bf16.h>
#include <math.h>
#include <cstdint>

#define BB 64
#define CINN 64
#define COUTT 128
#define NPIX 1024
#define TC 4

// fused SMEM: A double buffer 2x64KB = 131072, W at 131072 (40 rows x 272B = 10880),
// Ys[36864 f32] = 147456 aliases everything post-GEMM, red at 147456.
#define SM_AB 0
#define SM_W  131072
#define SM_RED 147456
#define SMEM_TOTAL 147584

__device__ uint4 A_g[BB * 4 * 4096];   // 16MB: per (b,chunk) 64KB tf32 plane, ldmatrix-swizzled
__device__ float g_psum[COUTT * BB];
__device__ float g_psumsq[COUTT * BB];
__device__ float g_scale[COUTT];
__device__ float g_shift[COUTT];

__device__ __forceinline__ uint32_t smem_u32(const void* p) {
    uint32_t a;
    asm("{ .reg .u64 t; cvta.to.shared.u64 t, %1; cvt.u32.u64 %0, t; }" : "=r"(a) : "l"(p));
    return a;
}
__device__ __forceinline__ void cp16(uint32_t dst, const void* src) {
    asm volatile("cp.async.cg.shared.global [%0], [%1], 16;" :: "r"(dst), "l"(src) : "memory");
}
__device__ __forceinline__ void ldmat4(uint32_t* r, uint32_t addr) {
    asm volatile("ldmatrix.sync.aligned.m8n8.x4.shared.b16 {%0,%1,%2,%3}, [%4];"
        : "=r"(r[0]), "=r"(r[1]), "=r"(r[2]), "=r"(r[3]) : "r"(addr));
}
__device__ __forceinline__ void mma_tf32(float* d, const uint32_t* a, const uint32_t* b) {
    asm volatile("mma.sync.aligned.m16n8k8.row.col.f32.tf32.tf32.f32 "
        "{%0,%1,%2,%3}, {%4,%5,%6,%7}, {%8,%9}, {%0,%1,%2,%3};"
        : "+f"(d[0]), "+f"(d[1]), "+f"(d[2]), "+f"(d[3])
        : "r"(a[0]), "r"(a[1]), "r"(a[2]), "r"(a[3]), "r"(b[0]), "r"(b[1]));
}
__device__ __forceinline__ uint32_t to_tf32(float f) {
    uint32_t o;
    asm("cvt.rna.tf32.f32 %0, %1;" : "=r"(o) : "f"(f));
    return o;
}
__device__ __forceinline__ int fd3(int a) { return (a + 24) / 3 - 8; }  // floor(a/3), a>=-24

// ---- prologue: per (chunk=16 cin, b) build tf32 plane [1024 px][16 k] with ldmatrix swizzle.
// 16B unit u (k4-group 0..3) of row px stored at slot u ^ ((px>>1)&3).
__global__ void __launch_bounds__(512) build_A(const float* __restrict__ x)
{
    extern __shared__ float Xs[];   // [16][1032]
    const int tid = threadIdx.x, chunk = blockIdx.x, b = blockIdx.y;
    const float4* xg = (const float4*)(x + (size_t)b * CINN * NPIX + chunk * 16 * NPIX);
#pragma unroll
    for (int j = 0; j < 8; j++) {
        int idx = tid + 512 * j;
        int ci = idx >> 8, px4 = idx & 255;
        *(float4*)(Xs + ci * 1032 + px4 * 4) = xg[idx];
    }
    __syncthreads();
    uint4* pb = A_g + (size_t)(b * 4 + chunk) * 4096;
#pragma unroll
    for (int rep = 0; rep < 2; rep++) {
        int px = tid + rep * 512;
        int s = (px >> 1) & 3;
#pragma unroll
        for (int u = 0; u < 4; u++) {
            uint4 v;
            v.x = to_tf32(Xs[(4 * u + 0) * 1032 + px]);
            v.y = to_tf32(Xs[(4 * u + 1) * 1032 + px]);
            v.z = to_tf32(Xs[(4 * u + 2) * 1032 + px]);
            v.w = to_tf32(Xs[(4 * u + 3) * 1032 + px]);
            pb[px * 4 + (u ^ s)] = v;
        }
    }
}

__global__ void __launch_bounds__(512, 1)
fused_kernel(const int* __restrict__ hh, const int* __restrict__ wwp,
             const float* __restrict__ weight, const float* __restrict__ bias,
             float* __restrict__ out)
{
    extern __shared__ char smem[];
    const uint32_t sb = smem_u32(smem);
    float* Ys = (float*)smem;
    const int tid = threadIdx.x, wid = tid >> 5, l = tid & 31;
    const int b = blockIdx.y, co0 = blockIdx.x * TC;

    // zero W region (rows 36..39 must read as 0)
    for (int i = tid; i < 2720; i += 512) *(uint32_t*)(smem + SM_W + 4 * i) = 0u;
    __syncthreads();
    // weights tf32: row n = tap*4+c, 68-word (272B) stride for conflict-free B-frag LDS
    for (int i = tid; i < TC * CINN * 9; i += 512) {
        int c = i / 576, r = i - c * 576, ci = r / 9, tap = r - ci * 9;
        float w = weight[(co0 + c) * 576 + ci * 9 + tap];
        *(uint32_t*)(smem + SM_W + (tap * 4 + c) * 272 + ci * 4) = to_tf32(w);
    }
    // stage chunk 0
    {
        const char* src = (const char*)(A_g + (size_t)(b * 4) * 4096);
#pragma unroll
        for (int j = 0; j < 8; j++) {
            int i = tid + 512 * j;
            cp16(sb + SM_AB + i * 16, src + i * 16);
        }
        asm volatile("cp.async.commit_group;" ::: "memory");
    }
    __syncthreads();

    float acc[4][5][4];
#pragma unroll
    for (int mt = 0; mt < 4; mt++)
#pragma unroll
        for (int nt = 0; nt < 5; nt++)
#pragma unroll
            for (int k = 0; k < 4; k++) acc[mt][nt][k] = 0.f;

    const int lq = l & 3, ln = l >> 2;
    const int px0 = wid * 64;
    // ldmatrix per-lane row px and unit: px = px0 + mt*16 + (l&15), u = 2*kk + (l>>4)
    const int lrow = l & 15, lu = l >> 4;

    for (int ch = 0; ch < 4; ch++) {
        asm volatile("cp.async.wait_group 0;" ::: "memory");
        __syncthreads();
        if (ch < 3) {
            const char* src = (const char*)(A_g + (size_t)(b * 4 + ch + 1) * 4096);
            uint32_t dbuf = sb + SM_AB + ((ch + 1) & 1) * 65536;
#pragma unroll
            for (int j = 0; j < 8; j++) {
                int i = tid + 512 * j;
                cp16(dbuf + i * 16, src + i * 16);
            }
            asm volatile("cp.async.commit_group;" ::: "memory");
        }
        // B fragments: b0 k = ch*16 + kk*8 + lq, b1 = +4; n = nt*8 + ln
        uint32_t bf[5][2][2];
#pragma unroll
        for (int nt = 0; nt < 5; nt++)
#pragma unroll
            for (int kk = 0; kk < 2; kk++) {
                int base = SM_W + (nt * 8 + ln) * 272 + (ch * 16 + kk * 8 + lq) * 4;
                bf[nt][kk][0] = *(uint32_t*)(smem + base);
                bf[nt][kk][1] = *(uint32_t*)(smem + base + 16);
            }
        const uint32_t abase = sb + SM_AB + (ch & 1) * 65536;
#pragma unroll
        for (int mt = 0; mt < 4; mt++) {
            int px = px0 + mt * 16 + lrow;
#pragma unroll
            for (int kk = 0; kk < 2; kk++) {
                uint32_t a[4];
                int u = 2 * kk + lu;
                ldmat4(a, abase + (uint32_t)px * 64 + (uint32_t)((u ^ ((px >> 1) & 3)) << 4));
#pragma unroll
                for (int nt = 0; nt < 5; nt++) mma_tf32(acc[mt][nt], a, bf[nt][kk]);
            }
        }
    }
    __syncthreads();   // all SMEM A/W reads done; Ys may overwrite

    // readout: D frag m16n8: d0/d1 row ln cols 2lq,2lq+1; d2/d3 row ln+8
#pragma unroll
    for (int mt = 0; mt < 4; mt++)
#pragma unroll
        for (int nt = 0; nt < 5; nt++) {
            int c0 = nt * 8 + 2 * lq;
            if (nt == 4 && lq >= 2) continue;  // cols 36..39 unused
            int px = px0 + mt * 16 + ln;
            Ys[c0 * NPIX + px]            = acc[mt][nt][0];
            Ys[(c0 + 1) * NPIX + px]      = acc[mt][nt][1];
            Ys[c0 * NPIX + px + 8]        = acc[mt][nt][2];
            Ys[(c0 + 1) * NPIX + px + 8]  = acc[mt][nt][3];
        }
    __syncthreads();

    // ---- combine with column dedup: Ys col c = tap*4 + co_l ----
    const int co_l = tid >> 7, lane128 = tid & 127;
    int dh = 96 / hh[b];  if (dh < 1) dh = 1;
    int dw = 96 / wwp[b]; if (dw < 1) dw = 1;
    int rv[3][2]; bool rsel[3][3];
    int  dcl[3], dch[3]; bool cdup[3], csel[3][3];
#pragma unroll
    for (int k = 0; k < 3; k++) {
        int d0 = fd3((k - 1) * dh), d1 = fd3(1 + (k - 1) * dh), d2 = fd3(2 + (k - 1) * dh);
        rv[k][0] = d0; rv[k][1] = d2;
        rsel[k][0] = false; rsel[k][1] = (d1 != d0); rsel[k][2] = (d2 != d0);
        int c0 = fd3((k - 1) * dw), c1 = fd3(1 + (k - 1) * dw), c2 = fd3(2 + (k - 1) * dw);
        dcl[k] = c0; dch[k] = c2; cdup[k] = (c2 != c0);
        csel[k][0] = false; csel[k][1] = (c1 != c0); csel[k][2] = (c2 != c0);
    }
    const float bias_v = bias[co0 + co_l];
    float lsum = 0.f, lsq = 0.f;
#pragma unroll 1
    for (int j = 0; j < 8; j++) {
        int pix = lane128 + (j << 7), py = pix >> 5, px = pix & 31;
        float RS[3][2][3];
#pragma unroll
        for (int ki = 0; ki < 3; ki++)
#pragma unroll
            for (int v = 0; v < 2; v++) {
                int row = py + rv[ki][v];
                bool rok = (unsigned)row < 32u;
                int rb = row * 32;
                float L0[3], L1[3];
#pragma unroll
                for (int kj = 0; kj < 3; kj++) {
                    const float* P = &Ys[((ki * 3 + kj) * TC + co_l) * NPIX + rb];
                    int cA = px + dcl[kj];
                    L0[kj] = (rok && (unsigned)cA < 32u) ? P[cA] : 0.f;
                    if (cdup[kj]) {
                        int cB = px + dch[kj];
                        L1[kj] = (rok && (unsigned)cB < 32u) ? P[cB] : 0.f;
                    } else L1[kj] = L0[kj];
                }
#pragma unroll
                for (int s = 0; s < 3; s++)
                    RS[ki][v][s] = L0[1] + (csel[0][s] ? L1[0] : L0[0])
                                         + (csel[2][s] ? L1[2] : L0[2]);
            }
        float mx = -INFINITY;
#pragma unroll
        for (int r = 0; r < 3; r++)
#pragma unroll
            for (int s = 0; s < 3; s++) {
                float v0 = rsel[0][r] ? RS[0][1][s] : RS[0][0][s];
                float v1 = rsel[1][r] ? RS[1][1][s] : RS[1][0][s];
                float v2 = rsel[2][r] ? RS[2][1][s] : RS[2][0][s];
                mx = fmaxf(mx, bias_v + v0 + v1 + v2);
            }
        out[((size_t)b * COUTT + co0 + co_l) * NPIX + pix] = mx;
        lsum += mx; lsq += mx * mx;
    }
#pragma unroll
    for (int o = 16; o > 0; o >>= 1) {
        lsum += __shfl_xor_sync(0xFFFFFFFFu, lsum, o);
        lsq  += __shfl_xor_sync(0xFFFFFFFFu, lsq,  o);
    }
    __syncthreads();
    float* red = (float*)(smem + SM_RED);
    if (l == 0) { red[wid * 2] = lsum; red[wid * 2 + 1] = lsq; }
    __syncthreads();
    if (tid < TC) {
        int c = tid;
        float s = red[8*c] + red[8*c+2] + red[8*c+4] + red[8*c+6];
        float q = red[8*c+1] + red[8*c+3] + red[8*c+5] + red[8*c+7];
        g_psum[(co0 + c) * BB + b] = s;
        g_psumsq[(co0 + c) * BB + b] = q;
    }
}

__global__ void stats_kernel(const float* __restrict__ gamma, const float* __restrict__ beta)
{
    int c = threadIdx.x;
    float s = 0.f, q = 0.f;
#pragma unroll 8
    for (int i = 0; i < BB; i++) { s += g_psum[c * BB + i]; q += g_psumsq[c * BB + i]; }
    const float inv = 1.0f / 65536.0f;
    float mean = s * inv, var = q * inv - mean * mean;
    float sc = gamma[c] * rsqrtf(var + 1e-5f);
    g_scale[c] = sc;
    g_shift[c] = beta[c] - mean * sc;
}

__global__ void __launch_bounds__(1024)
apply_kernel(float* __restrict__ out)
{
    int i0 = blockIdx.x * 4096 + threadIdx.x;
#pragma unroll
    for (int j = 0; j < 4; j++) {
        int i = i0 + j * 1024;
        int c = (i >> 8) & 127;
        float4 v = ((float4*)out)[i];
        float sc = g_scale[c], sh = g_shift[c];
        v.x = fmaxf(fmaf(v.x, sc, sh), 0.f);
        v.y = fmaxf(fmaf(v.y, sc, sh), 0.f);
        v.z = fmaxf(fmaf(v.z, sc, sh), 0.f);
        v.w = fmaxf(fmaf(v.w, sc, sh), 0.f);
        ((float4*)out)[i] = v;
    }
}

extern "C" void kernel_launch(void* const* d_in, const int* in_sizes, int n_in,
                              void* d_out, int out_size)
{
    const float* x      = (const float*)d_in[0];
    const int*   h      = (const int*)  d_in[1];
    const int*   w      = (const int*)  d_in[2];
    const float* weight = (const float*)d_in[3];
    const float* bias   = (const float*)d_in[4];
    const float* gamma  = (const float*)d_in[5];
    const float* beta   = (const float*)d_in[6];
    float* out = (float*)d_out;

    cudaFuncSetAttribute(build_A, cudaFuncAttributeMaxDynamicSharedMemorySize, 66048);
    cudaFuncSetAttribute(fused_kernel, cudaFuncAttributeMaxDynamicSharedMemorySize, SMEM_TOTAL);

    build_A<<<dim3(4, BB), 512, 66048>>>(x);
    fused_kernel<<<dim3(COUTT / TC, BB), 512, SMEM_TOTAL>>>(h, w, weight, bias, out);
    stats_kernel<<<1, 128>>>(gamma, beta);
    apply_kernel<<<512, 1024>>>(out);
}

// round 6
// speedup vs baseline: 1.8001x; 1.0681x over previous
#include <cuda_runtime.h>
#include <cuda_bf16.h>
#include <math.h>
#include <cstdint>

#define BB 64
#define CINN 64
#define COUTT 128
#define NPIX 1024
#define TC 4

// fused SMEM: Ys[36864 f32] = 147456 bytes; W region (40 rows x 272B) aliases Ys tail at
// 131072 (W read only during GEMM, Ys written only after GEMM sync). red at 147456.
#define SM_W  131072
#define SM_RED 147456
#define SMEM_TOTAL 147584

// A_g: per (b,chunk=16cin) plane of 4096 uint4 in MMA-fragment order:
// addr = (mtile*64 + kk*32 + lane), uint4 = {a0,a1,a2,a3} of m16n8k8 tf32 A fragment
// for rows mtile*16..+15, k = chunk*16 + kk*8 ..+7.
__device__ uint4 A_g[BB * 4 * 4096];
__device__ float g_psum[COUTT * BB];
__device__ float g_psumsq[COUTT * BB];
__device__ float g_scale[COUTT];
__device__ float g_shift[COUTT];

__device__ __forceinline__ void mma_tf32(float* d, const uint32_t* a, const uint32_t* b) {
    asm volatile("mma.sync.aligned.m16n8k8.row.col.f32.tf32.tf32.f32 "
        "{%0,%1,%2,%3}, {%4,%5,%6,%7}, {%8,%9}, {%0,%1,%2,%3};"
        : "+f"(d[0]), "+f"(d[1]), "+f"(d[2]), "+f"(d[3])
        : "r"(a[0]), "r"(a[1]), "r"(a[2]), "r"(a[3]), "r"(b[0]), "r"(b[1]));
}
__device__ __forceinline__ uint32_t to_tf32(float f) {
    uint32_t o;
    asm("cvt.rna.tf32.f32 %0, %1;" : "=r"(o) : "f"(f));
    return o;
}
__device__ __forceinline__ int fd3(int a) { return (a + 24) / 3 - 8; }  // floor(a/3), a>=-24

// ---- prologue: per (chunk,b) emit tf32 A plane in fragment order ----
__global__ void __launch_bounds__(512) build_A(const float* __restrict__ x)
{
    extern __shared__ float Xs[];   // [16][1032]
    const int tid = threadIdx.x, chunk = blockIdx.x, b = blockIdx.y;
    const float4* xg = (const float4*)(x + (size_t)b * CINN * NPIX + chunk * 16 * NPIX);
#pragma unroll
    for (int j = 0; j < 8; j++) {
        int idx = tid + 512 * j;
        int ci = idx >> 8, px4 = idx & 255;
        *(float4*)(Xs + ci * 1032 + px4 * 4) = xg[idx];
    }
    __syncthreads();
    uint4* pb = A_g + (size_t)(b * 4 + chunk) * 4096;
#pragma unroll
    for (int j = 0; j < 8; j++) {
        int idx = tid + 512 * j;
        int l = idx & 31, t = l & 3, g = l >> 2;
        int kk = (idx >> 5) & 1, mtile = idx >> 6;
        int px = mtile * 16 + g, k = kk * 8 + t;
        uint4 v;
        v.x = to_tf32(Xs[k * 1032 + px]);          // a0: (g,   t)
        v.y = to_tf32(Xs[k * 1032 + px + 8]);      // a1: (g+8, t)
        v.z = to_tf32(Xs[(k + 4) * 1032 + px]);    // a2: (g,   t+4)
        v.w = to_tf32(Xs[(k + 4) * 1032 + px + 8]);// a3: (g+8, t+4)
        pb[idx] = v;
    }
}

__global__ void __launch_bounds__(512, 1)
fused_kernel(const int* __restrict__ hh, const int* __restrict__ wwp,
             const float* __restrict__ weight, const float* __restrict__ bias,
             float* __restrict__ out)
{
    extern __shared__ char smem[];
    float* Ys = (float*)smem;
    const int tid = threadIdx.x, wid = tid >> 5, l = tid & 31;
    const int b = blockIdx.y, co0 = blockIdx.x * TC;

    // zero W region (rows 36..39 must read as 0)
    for (int i = tid; i < 2720; i += 512) *(uint32_t*)(smem + SM_W + 4 * i) = 0u;
    __syncthreads();
    // weights tf32: row n = tap*4+c, 272B stride (68 words -> conflict-free B-frag LDS)
    for (int i = tid; i < TC * CINN * 9; i += 512) {
        int c = i / 576, r = i - c * 576, ci = r / 9, tap = r - ci * 9;
        float w = weight[(co0 + c) * 576 + ci * 9 + tap];
        *(uint32_t*)(smem + SM_W + (tap * 4 + c) * 272 + ci * 4) = to_tf32(w);
    }
    __syncthreads();

    float acc[4][5][4];
#pragma unroll
    for (int mt = 0; mt < 4; mt++)
#pragma unroll
        for (int nt = 0; nt < 5; nt++)
#pragma unroll
            for (int k = 0; k < 4; k++) acc[mt][nt][k] = 0.f;

    const int lq = l & 3, ln = l >> 2;
    const int px0 = wid * 64;

#pragma unroll 1
    for (int ch = 0; ch < 4; ch++) {
        const uint4* pb = A_g + (size_t)(b * 4 + ch) * 4096;
#pragma unroll
        for (int kk = 0; kk < 2; kk++) {
            uint32_t bf[5][2];
#pragma unroll
            for (int nt = 0; nt < 5; nt++) {
                int base = SM_W + (nt * 8 + ln) * 272 + (ch * 16 + kk * 8 + lq) * 4;
                bf[nt][0] = *(uint32_t*)(smem + base);
                bf[nt][1] = *(uint32_t*)(smem + base + 16);
            }
#pragma unroll
            for (int mt = 0; mt < 4; mt++) {
                uint4 a = pb[(wid * 4 + mt) * 64 + kk * 32 + l];
#pragma unroll
                for (int nt = 0; nt < 5; nt++) mma_tf32(acc[mt][nt], (const uint32_t*)&a, bf[nt]);
            }
        }
    }
    __syncthreads();   // W reads done; Ys (aliasing W tail) may be written

    // readout: D frag m16n8: d0/d1 row ln cols 2lq,2lq+1; d2/d3 row ln+8
#pragma unroll
    for (int mt = 0; mt < 4; mt++)
#pragma unroll
        for (int nt = 0; nt < 5; nt++) {
            int c0 = nt * 8 + 2 * lq;
            if (nt == 4 && lq >= 2) continue;  // cols 36..39 unused
            int px = px0 + mt * 16 + ln;
            Ys[c0 * NPIX + px]            = acc[mt][nt][0];
            Ys[(c0 + 1) * NPIX + px]      = acc[mt][nt][1];
            Ys[c0 * NPIX + px + 8]        = acc[mt][nt][2];
            Ys[(c0 + 1) * NPIX + px + 8]  = acc[mt][nt][3];
        }
    __syncthreads();

    // ---- combine with row/col dedup: Ys col c = tap*4 + co_l ----
    const int co_l = tid >> 7, lane128 = tid & 127;
    int dh = 96 / hh[b];  if (dh < 1) dh = 1;
    int dw = 96 / wwp[b]; if (dw < 1) dw = 1;
    int rv[3][2]; bool rsel[3][3];
    int  dcl[3], dch[3]; bool cdup[3], csel[3][3];
#pragma unroll
    for (int k = 0; k < 3; k++) {
        int d0 = fd3((k - 1) * dh), d1 = fd3(1 + (k - 1) * dh), d2 = fd3(2 + (k - 1) * dh);
        rv[k][0] = d0; rv[k][1] = d2;
        rsel[k][0] = false; rsel[k][1] = (d1 != d0); rsel[k][2] = (d2 != d0);
        int c0 = fd3((k - 1) * dw), c1 = fd3(1 + (k - 1) * dw), c2 = fd3(2 + (k - 1) * dw);
        dcl[k] = c0; dch[k] = c2; cdup[k] = (c2 != c0);
        csel[k][0] = false; csel[k][1] = (c1 != c0); csel[k][2] = (c2 != c0);
    }
    const float bias_v = bias[co0 + co_l];
    float lsum = 0.f, lsq = 0.f;
#pragma unroll 2
    for (int j = 0; j < 8; j++) {
        int pix = lane128 + (j << 7), py = pix >> 5, px = pix & 31;
        float RS[3][2][3];
#pragma unroll
        for (int ki = 0; ki < 3; ki++)
#pragma unroll
            for (int v = 0; v < 2; v++) {
                int row = py + rv[ki][v];
                bool rok = (unsigned)row < 32u;
                int rb = row * 32;
                float L0[3], L1[3];
#pragma unroll
                for (int kj = 0; kj < 3; kj++) {
                    const float* P = &Ys[((ki * 3 + kj) * TC + co_l) * NPIX + rb];
                    int cA = px + dcl[kj];
                    L0[kj] = (rok && (unsigned)cA < 32u) ? P[cA] : 0.f;
                    if (cdup[kj]) {
                        int cB = px + dch[kj];
                        L1[kj] = (rok && (unsigned)cB < 32u) ? P[cB] : 0.f;
                    } else L1[kj] = L0[kj];
                }
#pragma unroll
                for (int s = 0; s < 3; s++)
                    RS[ki][v][s] = L0[1] + (csel[0][s] ? L1[0] : L0[0])
                                         + (csel[2][s] ? L1[2] : L0[2]);
            }
        float mx = -INFINITY;
#pragma unroll
        for (int r = 0; r < 3; r++)
#pragma unroll
            for (int s = 0; s < 3; s++) {
                float v0 = rsel[0][r] ? RS[0][1][s] : RS[0][0][s];
                float v1 = rsel[1][r] ? RS[1][1][s] : RS[1][0][s];
                float v2 = rsel[2][r] ? RS[2][1][s] : RS[2][0][s];
                mx = fmaxf(mx, bias_v + v0 + v1 + v2);
            }
        out[((size_t)b * COUTT + co0 + co_l) * NPIX + pix] = mx;
        lsum += mx; lsq += mx * mx;
    }
#pragma unroll
    for (int o = 16; o > 0; o >>= 1) {
        lsum += __shfl_xor_sync(0xFFFFFFFFu, lsum, o);
        lsq  += __shfl_xor_sync(0xFFFFFFFFu, lsq,  o);
    }
    __syncthreads();
    float* red = (float*)(smem + SM_RED);
    if (l == 0) { red[wid * 2] = lsum; red[wid * 2 + 1] = lsq; }
    __syncthreads();
    if (tid < TC) {
        int c = tid;
        float s = red[8*c] + red[8*c+2] + red[8*c+4] + red[8*c+6];
        float q = red[8*c+1] + red[8*c+3] + red[8*c+5] + red[8*c+7];
        g_psum[(co0 + c) * BB + b] = s;
        g_psumsq[(co0 + c) * BB + b] = q;
    }
}

// warp-per-channel: grid 4 x 1024 threads = 128 warps
__global__ void __launch_bounds__(1024)
stats_kernel(const float* __restrict__ gamma, const float* __restrict__ beta)
{
    int gw = (blockIdx.x * 1024 + threadIdx.x) >> 5;   // channel 0..127
    int l = threadIdx.x & 31;
    float s = g_psum[gw * BB + l] + g_psum[gw * BB + 32 + l];
    float q = g_psumsq[gw * BB + l] + g_psumsq[gw * BB + 32 + l];
#pragma unroll
    for (int o = 16; o > 0; o >>= 1) {
        s += __shfl_xor_sync(0xFFFFFFFFu, s, o);
        q += __shfl_xor_sync(0xFFFFFFFFu, q, o);
    }
    if (l == 0) {
        const float inv = 1.0f / 65536.0f;
        float mean = s * inv, var = q * inv - mean * mean;
        float sc = gamma[gw] * rsqrtf(var + 1e-5f);
        g_scale[gw] = sc;
        g_shift[gw] = beta[gw] - mean * sc;
    }
}

__global__ void __launch_bounds__(1024)
apply_kernel(float* __restrict__ out)
{
    int i0 = blockIdx.x * 4096 + threadIdx.x;
#pragma unroll
    for (int j = 0; j < 4; j++) {
        int i = i0 + j * 1024;
        int c = (i >> 8) & 127;
        float4 v = ((float4*)out)[i];
        float sc = g_scale[c], sh = g_shift[c];
        v.x = fmaxf(fmaf(v.x, sc, sh), 0.f);
        v.y = fmaxf(fmaf(v.y, sc, sh), 0.f);
        v.z = fmaxf(fmaf(v.z, sc, sh), 0.f);
        v.w = fmaxf(fmaf(v.w, sc, sh), 0.f);
        ((float4*)out)[i] = v;
    }
}

extern "C" void kernel_launch(void* const* d_in, const int* in_sizes, int n_in,
                              void* d_out, int out_size)
{
    const float* x      = (const float*)d_in[0];
    const int*   h      = (const int*)  d_in[1];
    const int*   w      = (const int*)  d_in[2];
    const float* weight = (const float*)d_in[3];
    const float* bias   = (const float*)d_in[4];
    const float* gamma  = (const float*)d_in[5];
    const float* beta   = (const float*)d_in[6];
    float* out = (float*)d_out;

    cudaFuncSetAttribute(build_A, cudaFuncAttributeMaxDynamicSharedMemorySize, 66048);
    cudaFuncSetAttribute(fused_kernel, cudaFuncAttributeMaxDynamicSharedMemorySize, SMEM_TOTAL);

    build_A<<<dim3(4, BB), 512, 66048>>>(x);
    fused_kernel<<<dim3(COUTT / TC, BB), 512, SMEM_TOTAL>>>(h, w, weight, bias, out);
    stats_kernel<<<4, 1024>>>(gamma, beta);
    apply_kernel<<<512, 1024>>>(out);
}